// round 16
// baseline (speedup 1.0000x reference)
#include <cuda_runtime.h>
#include <cuda_bf16.h>
#include <mma.h>
#include <cstdint>

using namespace nvcuda;

// Problem constants
#define Bb    8
#define Dh    256
#define Tt    8192
#define NQ    8
#define BINS  1024

#define POS      64
#define THREADS  128
#define NCTA     ((Bb * Tt) / POS)   // 1024
#define NCHUNK   (NQ * 32)           // 256 B-chunks of 32 codewords

// Output layout (float32 concat): quantized [B,D,T], codes [NQ,B,T], bw, loss
#define Q_ELEMS   ((size_t)Bb * Dh * Tt)
#define C_OFF     Q_ELEMS
#define C_ELEMS   ((size_t)NQ * Bb * Tt)
#define BW_OFF    (C_OFF + C_ELEMS)
#define LOSS_OFF  (BW_OFF + 1)

typedef unsigned int u32;

__device__ float g_half_cbsq[NQ * BINS];
__device__ float g_partials[NCTA];
__device__ __nv_bfloat16 g_cb_hi[NQ * BINS * Dh];   // 4 MB
__device__ __nv_bfloat16 g_cb_lo[NQ * BINS * Dh];   // 4 MB

// ---- smem layout (bytes) ----
#define OFF_CODES 0                         // 64 ints
#define OFF_WLOSS 256                       // 4 floats
#define OFF_HQ    512                       // 1024 f32
#define OFF_RES   4608                      // 64 x 260 f32
#define RES_STR   260
#define OFF_AHI   71168                     // 64 x 272 bf16
#define OFF_ALO   105984                    // 64 x 272 bf16
#define A_STR     272
#define OFF_BHI   140800                    // 2 x 32 x 272 bf16
#define OFF_BLO   175616                    // 2 x 32 x 272 bf16
#define B_STR     272
#define B_BUF_B   17408                     // bytes per B buffer (32*272*2)
#define OFF_CS    210432                    // 64 x 40 f32
#define C_STR     40
#define SMEM_TOTAL 220672

#define MARGIN 0.02f

__device__ __forceinline__ u32 smem_u32(const void* p) {
    return (u32)__cvta_generic_to_shared(p);
}
__device__ __forceinline__ void cp16(u32 dst, const void* src) {
    asm volatile("cp.async.cg.shared.global [%0], [%1], 16;" :: "r"(dst), "l"(src));
}
__device__ __forceinline__ void cp_commit() {
    asm volatile("cp.async.commit_group;" ::: "memory");
}
__device__ __forceinline__ void cp_wait0() {
    asm volatile("cp.async.wait_group 0;" ::: "memory");
}

// ---------------------------------------------------------------------------
// Prep: per codeword row — 0.5*||c||^2 (fp32) and bf16 hi/lo split.
// ---------------------------------------------------------------------------
__global__ void prep_kernel(const float* __restrict__ cb) {
    int row = (blockIdx.x * blockDim.x + threadIdx.x) >> 5;
    int lane = threadIdx.x & 31;
    if (row >= NQ * BINS) return;
    const float* src = cb + (size_t)row * Dh;
    float s = 0.f;
    for (int d = lane; d < Dh; d += 32) {
        float v = src[d];
        s += v * v;
        __nv_bfloat16 hi = __float2bfloat16(v);
        __nv_bfloat16 lo = __float2bfloat16(v - __bfloat162float(hi));
        g_cb_hi[(size_t)row * Dh + d] = hi;
        g_cb_lo[(size_t)row * Dh + d] = lo;
    }
    #pragma unroll
    for (int o = 16; o; o >>= 1) s += __shfl_xor_sync(0xffffffffu, s, o);
    if (lane == 0) g_half_cbsq[row] = 0.5f * s;
}

// ---------------------------------------------------------------------------
// Main WMMA RVQ kernel. CTA = 64 positions, 4 warps.
// Warp w owns position rows [w*16, w*16+16). Scores for a 32-codeword chunk
// are computed as a 64x32 bf16x3 split-GEMM into fp32, stored to smem, and
// folded per position (thread tid<64 owns position tid).
// ---------------------------------------------------------------------------
__global__ void __launch_bounds__(THREADS, 1)
rvq_wmma_kernel(const float* __restrict__ x, const float* __restrict__ cb,
                float* __restrict__ out) {
    extern __shared__ char smem[];
    const u32 sb = smem_u32(smem);
    const int tid = threadIdx.x;
    const int w = tid >> 5;
    const int b = blockIdx.x >> 7;            // 128 CTAs per batch entry
    const int t0 = (blockIdx.x & 127) * POS;
    const size_t xbase = (size_t)b * Dh * Tt + t0;

    float* res = (float*)(smem + OFF_RES);
    float* hq_sm = (float*)(smem + OFF_HQ);
    float* csm = (float*)(smem + OFF_CS);
    int* codes_sm = (int*)(smem + OFF_CODES);
    __nv_bfloat16* Ahi = (__nv_bfloat16*)(smem + OFF_AHI);
    __nv_bfloat16* Alo = (__nv_bfloat16*)(smem + OFF_ALO);

    // Load x tile into residual smem (coalesced 64-float rows per d)
    for (int i = tid; i < POS * Dh; i += THREADS) {
        int d = i >> 6, tt = i & 63;
        res[tt * RES_STR + d] = x[xbase + (size_t)d * Tt + tt];
    }
    float sqacc = 0.f;

    // Stage B chunk gc: stage s2 = gc>>5, codewords [p2*32, p2*32+32).
    // 1024 16B copies per buffer (hi and lo), 8 per thread each.
    auto stageB = [&](int gc) {
        int s2 = gc >> 5, p2 = gc & 31;
        const char* srcH = (const char*)(g_cb_hi + ((size_t)s2 * BINS + p2 * 32) * Dh);
        const char* srcL = (const char*)(g_cb_lo + ((size_t)s2 * BINS + p2 * 32) * Dh);
        u32 dstH = sb + OFF_BHI + (u32)(gc & 1) * B_BUF_B;
        u32 dstL = sb + OFF_BLO + (u32)(gc & 1) * B_BUF_B;
        #pragma unroll
        for (int i = 0; i < 8; i++) {
            int idx = tid + THREADS * i;       // 0..1023
            int r = idx >> 5, c16 = idx & 31;  // row (cw), 16B col
            u32 off = (u32)r * (B_STR * 2) + (u32)c16 * 16;
            size_t soff = (size_t)r * (Dh * 2) + (size_t)c16 * 16;
            cp16(dstH + off, srcH + soff);
            cp16(dstL + off, srcL + soff);
        }
        cp_commit();
    };

    stageB(0);
    __syncthreads();   // res tile visible

    for (int s = 0; s < NQ; s++) {
        // stage-local 0.5||c||^2
        for (int i = tid; i < BINS; i += THREADS)
            hq_sm[i] = g_half_cbsq[s * BINS + i];

        // residual -> bf16 hi/lo A tiles (pos-major rows)
        for (int i = tid; i < POS * Dh; i += THREADS) {
            int pos = i >> 8, d = i & 255;
            float f = res[pos * RES_STR + d];
            __nv_bfloat16 h = __float2bfloat16(f);
            __nv_bfloat16 l = __float2bfloat16(f - __bfloat162float(h));
            Ahi[pos * A_STR + d] = h;
            Alo[pos * A_STR + d] = l;
        }
        // visibility of A/hq is covered by the first chunk's barrier below

        float best = -3.4e38f, second = -3.4e38f;
        int bidx = 0, sidx = 0;

        for (int p = 0; p < 32; p++) {
            const int gc = s * 32 + p;
            const int cw0 = p * 32;

            cp_wait0();        // my staged portion of chunk gc landed
            __syncthreads();   // publish gc (+A/hq); all warps done w/ gc-1
            if (gc + 1 < NCHUNK) stageB(gc + 1);

            // ---- 64x32 = A(64x256) * B(256x32)^T via 3 bf16 products ----
            {
                wmma::fragment<wmma::accumulator, 16, 16, 16, float> acc[2][3];
                #pragma unroll
                for (int j = 0; j < 2; j++)
                    #pragma unroll
                    for (int q = 0; q < 3; q++)
                        wmma::fill_fragment(acc[j][q], 0.0f);

                const __nv_bfloat16* Ah = Ahi + (w * 16) * A_STR;
                const __nv_bfloat16* Al = Alo + (w * 16) * A_STR;
                const __nv_bfloat16* Bh =
                    (const __nv_bfloat16*)(smem + OFF_BHI + (gc & 1) * B_BUF_B);
                const __nv_bfloat16* Bl =
                    (const __nv_bfloat16*)(smem + OFF_BLO + (gc & 1) * B_BUF_B);

                #pragma unroll 4
                for (int k = 0; k < 16; k++) {
                    wmma::fragment<wmma::matrix_a, 16, 16, 16, __nv_bfloat16,
                                   wmma::row_major> ah, al;
                    wmma::load_matrix_sync(ah, Ah + k * 16, A_STR);
                    wmma::load_matrix_sync(al, Al + k * 16, A_STR);
                    #pragma unroll
                    for (int j = 0; j < 2; j++) {
                        wmma::fragment<wmma::matrix_b, 16, 16, 16, __nv_bfloat16,
                                       wmma::col_major> bh, bl;
                        wmma::load_matrix_sync(bh, Bh + (j * 16) * B_STR + k * 16,
                                               B_STR);
                        wmma::load_matrix_sync(bl, Bl + (j * 16) * B_STR + k * 16,
                                               B_STR);
                        wmma::mma_sync(acc[j][0], ah, bh, acc[j][0]);
                        wmma::mma_sync(acc[j][1], ah, bl, acc[j][1]);
                        wmma::mma_sync(acc[j][2], al, bh, acc[j][2]);
                    }
                }
                #pragma unroll
                for (int j = 0; j < 2; j++) {
                    #pragma unroll
                    for (int e = 0; e < acc[j][0].num_elements; e++)
                        acc[j][0].x[e] += acc[j][1].x[e] + acc[j][2].x[e];
                    wmma::store_matrix_sync(csm + (w * 16) * C_STR + j * 16,
                                            acc[j][0], C_STR, wmma::mem_row_major);
                }
            }
            __syncthreads();   // C visible; mma reads of B[gc] done

            // ---- fold: thread tid<64 owns position tid ----
            if (tid < POS) {
                const float* crow = &csm[tid * C_STR];
                const float* hqp = &hq_sm[cw0];
                #pragma unroll
                for (int c = 0; c < 32; c++) {
                    float sc = crow[c] - hqp[c];
                    if (sc > best) {
                        second = best; sidx = bidx;
                        best = sc; bidx = cw0 + c;
                    } else if (sc > second) {
                        second = sc; sidx = cw0 + c;
                    }
                }
            }
            // fold-vs-next-store hazard covered by next chunk's barrier
        }

        // ---- exact fp32 rescore of top-2 when approx gap < MARGIN ----
        if (tid < POS) {
            int bi = bidx;
            if (second > best - MARGIN) {
                const float* rr = &res[tid * RES_STR];
                const float* c1 = cb + ((size_t)s * BINS + bidx) * Dh;
                const float* c2 = cb + ((size_t)s * BINS + sidx) * Dh;
                float a0 = 0.f, a1 = 0.f, b0 = 0.f, b1 = 0.f;
                for (int d = 0; d < Dh; d += 2) {
                    a0 += rr[d] * c1[d];     a1 += rr[d + 1] * c1[d + 1];
                    b0 += rr[d] * c2[d];     b1 += rr[d + 1] * c2[d + 1];
                }
                float e1 = a0 + a1 - hq_sm[bidx];
                float e2 = b0 + b1 - hq_sm[sidx];
                if (e2 > e1 || (e2 == e1 && sidx < bidx)) bi = sidx;
            }
            codes_sm[tid] = bi;
            out[C_OFF + (size_t)(s * Bb + b) * Tt + t0 + tid] = (float)bi;
        }
        __syncthreads();

        // ---- cooperative residual update (coalesced codeword reads) ----
        for (int q = 0; q < POS; q++) {
            int ci = codes_sm[q];
            const float2* crow =
                (const float2*)(cb + ((size_t)s * BINS + ci) * Dh);
            float2 cv = crow[tid];
            float* rp = &res[q * RES_STR + 2 * tid];
            float r0 = rp[0] - cv.x, r1 = rp[1] - cv.y;
            rp[0] = r0; rp[1] = r1;
            sqacc += r0 * r0 + r1 * r1;
        }
        __syncthreads();
    }

    // quantized = x - r_final (coalesced)
    for (int i = tid; i < POS * Dh; i += THREADS) {
        int d = i >> 6, tt = i & 63;
        size_t gi = xbase + (size_t)d * Tt + tt;
        out[gi] = x[gi] - res[tt * RES_STR + d];
    }

    // deterministic loss partial
    float sq = sqacc;
    #pragma unroll
    for (int o = 16; o; o >>= 1) sq += __shfl_xor_sync(0xffffffffu, sq, o);
    float* wl = (float*)(smem + OFF_WLOSS);
    if ((tid & 31) == 0) wl[w] = sq;
    __syncthreads();
    if (tid == 0)
        g_partials[blockIdx.x] = wl[0] + wl[1] + wl[2] + wl[3];
}

// ---------------------------------------------------------------------------
__global__ void finalize_kernel(const int* __restrict__ sr_i,
                                float* __restrict__ out) {
    __shared__ float red[256];
    int tid = threadIdx.x;
    float s = 0.f;
    for (int i = tid; i < NCTA; i += 256) s += g_partials[i];
    red[tid] = s;
    __syncthreads();
    for (int o = 128; o; o >>= 1) {
        if (tid < o) red[tid] += red[tid + o];
        __syncthreads();
    }
    if (tid == 0) {
        out[LOSS_OFF] = 0.25f * red[0] / (float)((size_t)NQ * Bb * Tt * Dh);
        int iv = sr_i[0];
        float sr = (iv > 0 && iv < 1000000000) ? (float)iv : __int_as_float(iv);
        out[BW_OFF] = (float)NQ * 10.0f * sr / 1000.0f;
    }
}

// ---------------------------------------------------------------------------
extern "C" void kernel_launch(void* const* d_in, const int* in_sizes, int n_in,
                              void* d_out, int out_size) {
    const float* x  = (const float*)d_in[0];
    const int*   sr = (const int*)d_in[1];
    const float* cb = (const float*)d_in[2];
    float* out = (float*)d_out;

    static int smem_set = 0;
    if (!smem_set) {
        cudaFuncSetAttribute(rvq_wmma_kernel,
                             cudaFuncAttributeMaxDynamicSharedMemorySize,
                             SMEM_TOTAL);
        smem_set = 1;
    }

    prep_kernel<<<(NQ * BINS * 32 + 255) / 256, 256>>>(cb);
    rvq_wmma_kernel<<<NCTA, THREADS, SMEM_TOTAL>>>(x, cb, out);
    finalize_kernel<<<1, 256>>>(sr, out);
}